// round 1
// baseline (speedup 1.0000x reference)
#include <cuda_runtime.h>
#include <math.h>

// Problem dims
#define R_TOT 16384   // 16 * 32 * 32 rows of zf
#define NE    8192    // codebook entries
#define D     256     // embedding dim
#define NSPLIT 4
#define BM 128
#define BN 128
#define BK 16
#define COLS_PER_SPLIT (NE / NSPLIT)        // 2048
#define TILES_PER_SPLIT (COLS_PER_SPLIT/BN) // 16

// Output layout (float32, tuple members flattened & concatenated):
// loss(1), z_q(16,256,32,32)=4194304, perplexity(1),
// min_encodings(16384,8192)=134217728, min_idx(16384,1), second_idx(16384,1)
constexpr long O_LOSS = 0;
constexpr long O_ZQ   = 1;
constexpr long O_PERP = 4194305;
constexpr long O_ENC  = 4194306;
constexpr long O_MIN  = 138412034;  // O_ENC + 134217728
constexpr long O_SEC  = 138428418;  // O_MIN + 16384

// Scratch (no allocations allowed -> device globals)
__device__ double g_loss;
__device__ int    g_counts[NE];
__device__ float4 g_part[R_TOT * NSPLIT];   // (d1, i1-bits, d2, i2-bits) per split

// ---------------------------------------------------------------------------
// top-2 merge with jax.lax.top_k semantics: order by (dist asc, index asc)
// ---------------------------------------------------------------------------
__device__ __forceinline__ bool lessp(float ad, int ai, float bd, int bi) {
    return (ad < bd) || (ad == bd && ai < bi);
}
// merge ordered pair (od1,oi1)<=(od2,oi2) into ordered (d1,i1)<=(d2,i2)
__device__ __forceinline__ void merge2(float& d1, int& i1, float& d2, int& i2,
                                       float od1, int oi1, float od2, int oi2) {
    if (lessp(od1, oi1, d1, i1)) {
        if (lessp(d1, i1, od2, oi2)) { d2 = d1; i2 = i1; }
        else                         { d2 = od2; i2 = oi2; }
        d1 = od1; i1 = oi1;
    } else {
        if (lessp(od1, oi1, d2, i2)) { d2 = od1; i2 = oi1; }
    }
}

// ---------------------------------------------------------------------------
// K0: zero one-hot region (537MB) + counters
// ---------------------------------------------------------------------------
__global__ void vq_zero(float* __restrict__ out) {
    const long n2 = 134217728L / 2;             // float2 count (O_ENC*4 is 8B-aligned)
    float2* p = reinterpret_cast<float2*>(out + O_ENC);
    float2 z2; z2.x = 0.f; z2.y = 0.f;
    long stride = (long)gridDim.x * blockDim.x;
    for (long i = (long)blockIdx.x * blockDim.x + threadIdx.x; i < n2; i += stride)
        p[i] = z2;
    int g = blockIdx.x * blockDim.x + threadIdx.x;
    if (g < NE) g_counts[g] = 0;
    if (g == 0) g_loss = 0.0;
}

// ---------------------------------------------------------------------------
// K1: fused fp32 GEMM (scores) + per-row top-2 over a column split
//   z logical row i = b*1024 + h*32 + w ; element (i,c) at b*262144 + c*1024 + (i%1024)
// ---------------------------------------------------------------------------
__global__ __launch_bounds__(256) void vq_main(const float* __restrict__ z,
                                               const float* __restrict__ emb) {
    __shared__ float As[BK][BM];
    __shared__ float Bs[BK][BN];
    __shared__ float sA[BM];

    const int rb  = blockIdx.x;        // 0..127 row blocks (each inside one batch b)
    const int sp  = blockIdx.y;        // 0..3 column split
    const int tid = threadIdx.x;
    const int tx  = tid & 15;          // col group
    const int ty  = tid >> 4;          // row group
    const long zblock = (long)(rb >> 3) * 262144L + (long)(rb & 7) * 128L;

    // per-row |z|^2 (fp32; exact value order-invariant for the comparison, see analysis)
    if (tid < BM) {
        const float* p = z + zblock + tid;
        float a = 0.f;
        #pragma unroll 8
        for (int c = 0; c < D; c++) { float v = p[(long)c * 1024L]; a = fmaf(v, v, a); }
        sA[tid] = a;
    }
    __syncthreads();

    float myA[8];
    #pragma unroll
    for (int m = 0; m < 8; m++) myA[m] = sA[ty * 8 + m];

    float d1[8], d2[8]; int i1[8], i2[8];
    #pragma unroll
    for (int m = 0; m < 8; m++) { d1[m] = INFINITY; d2[m] = INFINITY; i1[m] = 0; i2[m] = 0; }

    for (int jt = 0; jt < TILES_PER_SPLIT; jt++) {
        const int j0 = sp * COLS_PER_SPLIT + jt * BN;
        float acc[8][8];
        #pragma unroll
        for (int m = 0; m < 8; m++)
            #pragma unroll
            for (int n = 0; n < 8; n++) acc[m][n] = 0.f;

        for (int kc = 0; kc < D / BK; kc++) {
            __syncthreads();
            // Stage z tile: As[k][m], contiguous-in-m global loads
            #pragma unroll
            for (int r = 0; r < 2; r++) {
                int idx = tid + r * 256;
                int c   = idx >> 5;
                int m4  = (idx & 31) << 2;
                float4 v = *reinterpret_cast<const float4*>(
                    z + zblock + (long)(kc * BK + c) * 1024L + m4);
                *reinterpret_cast<float4*>(&As[c][m4]) = v;
            }
            // Stage embedding tile: Bs[k][j] (transpose on store)
            #pragma unroll
            for (int r = 0; r < 2; r++) {
                int q4 = (tid >> 7) + 2 * r;     // 0..3 -> k sub-chunk
                int jj = tid & 127;
                float4 v = *reinterpret_cast<const float4*>(
                    emb + (long)(j0 + jj) * D + kc * BK + q4 * 4);
                Bs[q4 * 4 + 0][jj] = v.x;
                Bs[q4 * 4 + 1][jj] = v.y;
                Bs[q4 * 4 + 2][jj] = v.z;
                Bs[q4 * 4 + 3][jj] = v.w;
            }
            __syncthreads();
            #pragma unroll
            for (int k = 0; k < BK; k++) {
                float a[8], b[8];
                *reinterpret_cast<float4*>(&a[0]) = *reinterpret_cast<const float4*>(&As[k][ty * 8]);
                *reinterpret_cast<float4*>(&a[4]) = *reinterpret_cast<const float4*>(&As[k][ty * 8 + 4]);
                *reinterpret_cast<float4*>(&b[0]) = *reinterpret_cast<const float4*>(&Bs[k][tx * 8]);
                *reinterpret_cast<float4*>(&b[4]) = *reinterpret_cast<const float4*>(&Bs[k][tx * 8 + 4]);
                #pragma unroll
                for (int m = 0; m < 8; m++)
                    #pragma unroll
                    for (int n = 0; n < 8; n++)
                        acc[m][n] = fmaf(a[m], b[n], acc[m][n]);
            }
        }

        // dists = fl(A - 2*dot)  (single rounding; |e|^2 provably rounds away in the ref)
        #pragma unroll
        for (int m = 0; m < 8; m++) {
            #pragma unroll
            for (int n = 0; n < 8; n++) {
                float dd  = fmaf(-2.f, acc[m][n], myA[m]);
                int   jdx = j0 + tx * 8 + n;
                if (lessp(dd, jdx, d1[m], i1[m])) {
                    d2[m] = d1[m]; i2[m] = i1[m]; d1[m] = dd; i1[m] = jdx;
                } else if (lessp(dd, jdx, d2[m], i2[m])) {
                    d2[m] = dd; i2[m] = jdx;
                }
            }
        }
    }

    // Reduce top-2 across the 16 tx lanes (xor stays inside the 16-lane half-warp)
    #pragma unroll
    for (int m = 0; m < 8; m++) {
        #pragma unroll
        for (int off = 8; off >= 1; off >>= 1) {
            float od1 = __shfl_xor_sync(0xffffffffu, d1[m], off);
            int   oi1 = __shfl_xor_sync(0xffffffffu, i1[m], off);
            float od2 = __shfl_xor_sync(0xffffffffu, d2[m], off);
            int   oi2 = __shfl_xor_sync(0xffffffffu, i2[m], off);
            merge2(d1[m], i1[m], d2[m], i2[m], od1, oi1, od2, oi2);
        }
    }
    if (tx == 0) {
        #pragma unroll
        for (int m = 0; m < 8; m++) {
            int row = rb * BM + ty * 8 + m;
            g_part[row * NSPLIT + sp] =
                make_float4(d1[m], __int_as_float(i1[m]), d2[m], __int_as_float(i2[m]));
        }
    }
}

// ---------------------------------------------------------------------------
// K2: merge splits per row; write indices, one-hot, z_q; accumulate loss/counts
// ---------------------------------------------------------------------------
__global__ void vq_finalize(const float* __restrict__ z, const float* __restrict__ emb,
                            float* __restrict__ out) {
    int row = blockIdx.x * blockDim.x + threadIdx.x;
    if (row >= R_TOT) return;

    float d1 = INFINITY, d2 = INFINITY; int i1 = 0, i2 = 0;
    #pragma unroll
    for (int s = 0; s < NSPLIT; s++) {
        float4 p = g_part[row * NSPLIT + s];
        merge2(d1, i1, d2, i2, p.x, __float_as_int(p.y), p.z, __float_as_int(p.w));
    }

    out[O_MIN + row] = (float)i1;
    out[O_SEC + row] = (float)i2;
    out[O_ENC + (long)row * NE + i1] = 1.0f;
    atomicAdd(&g_counts[i1], 1);

    const long zoff = (long)(row >> 10) * 262144L + (long)(row & 1023);
    const float* e = emb + (long)i1 * D;
    double ls = 0.0;
    #pragma unroll 8
    for (int c = 0; c < D; c++) {
        float v = e[c];
        long  a = zoff + (long)c * 1024L;
        float diff = v - z[a];
        ls += (double)diff * (double)diff;
        out[O_ZQ + a] = v;   // straight-through z_q == quantized values
    }
    atomicAdd(&g_loss, ls);
}

// ---------------------------------------------------------------------------
// K3: scalars (loss, perplexity)
// ---------------------------------------------------------------------------
__global__ void vq_scalars(float* __restrict__ out) {
    __shared__ double sh[256];
    int t = threadIdx.x;
    double s = 0.0;
    for (int j = t; j < NE; j += 256) {
        double p = (double)g_counts[j] / 16384.0;
        s += p * log(p + 1e-10);
    }
    sh[t] = s;
    __syncthreads();
    for (int off = 128; off > 0; off >>= 1) {
        if (t < off) sh[t] += sh[t + off];
        __syncthreads();
    }
    if (t == 0) {
        out[O_PERP] = (float)exp(-sh[0]);
        out[O_LOSS] = (float)(1.25 * g_loss / 4194304.0);
    }
}

// ---------------------------------------------------------------------------
extern "C" void kernel_launch(void* const* d_in, const int* in_sizes, int n_in,
                              void* d_out, int out_size) {
    const float* z   = (const float*)d_in[0];   // (16,256,32,32)
    const float* emb = (const float*)d_in[1];   // (8192,256)
    float* out = (float*)d_out;

    vq_zero<<<4096, 256>>>(out);
    dim3 grid(R_TOT / BM, NSPLIT);
    vq_main<<<grid, 256>>>(z, emb);
    vq_finalize<<<R_TOT / 256, 256>>>(z, emb, out);
    vq_scalars<<<1, 256>>>(out);
}